// round 1
// baseline (speedup 1.0000x reference)
#include <cuda_runtime.h>
#include <cstdint>

#define DMODEL 512
#define DFF 2048
#define NEXP 8
#define TOPK 2
#define NMAX 32768
#define CAPMAX 10240

typedef unsigned long long ull;

// ---------------- scratch (static __device__: no allocation) ----------------
__device__ float  g_H [(size_t)NEXP * CAPMAX * DFF];   // gelu(X@W1+b1)
__device__ float  g_EO[(size_t)NEXP * CAPMAX * DMODEL]; // H@W2+b2
__device__ int    g_rowidx[NEXP * CAPMAX];              // slot -> token (-1 pad)
__device__ int    g_slot[NMAX * TOPK];                  // (tok,k) -> slot (0 if dropped)
__device__ float  g_wk  [NMAX * TOPK];                  // kept weight (0 if dropped)
__device__ int2   g_ti[NMAX];
__device__ float2 g_tw[NMAX];
__device__ int    g_cnt[NEXP];

// ---------------- helpers ----------------
__device__ __forceinline__ ull dupf(float a) {
    ull d; unsigned u = __float_as_uint(a);
    asm("mov.b64 %0, {%1, %1};" : "=l"(d) : "r"(u));
    return d;
}
__device__ __forceinline__ ull ffma2(ull a, ull b, ull c) {
    ull d;
    asm("fma.rn.f32x2 %0, %1, %2, %3;" : "=l"(d) : "l"(a), "l"(b), "l"(c));
    return d;
}
__device__ __forceinline__ float2 unpk(ull v) {
    unsigned lo, hi;
    asm("mov.b64 {%0, %1}, %2;" : "=r"(lo), "=r"(hi) : "l"(v));
    return make_float2(__uint_as_float(lo), __uint_as_float(hi));
}
__device__ __forceinline__ float gelu_exact(float v) {
    return 0.5f * v * (1.0f + erff(v * 0.7071067811865476f));
}

// ---------------- router: logits -> softmax -> top2 -> weights ----------------
__global__ void router_kernel(const float* __restrict__ x,
                              const float* __restrict__ Wr,
                              const float* __restrict__ br, int N) {
    int warp = (blockIdx.x * blockDim.x + threadIdx.x) >> 5;
    int lane = threadIdx.x & 31;
    if (warp >= N) return;
    const float* xr = x + (size_t)warp * DMODEL;
    float acc[8] = {0, 0, 0, 0, 0, 0, 0, 0};
    for (int d = lane; d < DMODEL; d += 32) {
        float xv = xr[d];
        float4 w0 = *(const float4*)(Wr + (size_t)d * 8);
        float4 w1 = *(const float4*)(Wr + (size_t)d * 8 + 4);
        acc[0] += xv * w0.x; acc[1] += xv * w0.y;
        acc[2] += xv * w0.z; acc[3] += xv * w0.w;
        acc[4] += xv * w1.x; acc[5] += xv * w1.y;
        acc[6] += xv * w1.z; acc[7] += xv * w1.w;
    }
    #pragma unroll
    for (int o = 16; o; o >>= 1) {
        #pragma unroll
        for (int e = 0; e < 8; e++)
            acc[e] += __shfl_xor_sync(0xFFFFFFFFu, acc[e], o);
    }
    if (lane == 0) {
        float l[8], p[8];
        float m = -1e30f;
        #pragma unroll
        for (int e = 0; e < 8; e++) { l[e] = acc[e] + br[e]; m = fmaxf(m, l[e]); }
        float s = 0.f;
        #pragma unroll
        for (int e = 0; e < 8; e++) { p[e] = expf(l[e] - m); s += p[e]; }
        float inv = 1.0f / s;
        #pragma unroll
        for (int e = 0; e < 8; e++) p[e] *= inv;
        int i1 = 0; float p1 = p[0];
        #pragma unroll
        for (int e = 1; e < 8; e++) if (p[e] > p1) { p1 = p[e]; i1 = e; }
        int i2 = -1; float p2 = -1.0f;
        #pragma unroll
        for (int e = 0; e < 8; e++) if (e != i1 && p[e] > p2) { p2 = p[e]; i2 = e; }
        float den = p1 + p2 + 1e-9f;
        g_ti[warp] = make_int2(i1, i2);
        g_tw[warp] = make_float2(p1 / den, p2 / den);
    }
}

// ---------------- dispatch: ordered capacity positions (deterministic scan) ----------------
__global__ void dispatch_kernel(int N, int cap) {
    const int T = 1024;
    int t = threadIdx.x;
    int slots = N * TOPK;
    int C = (slots + T - 1) / T;
    __shared__ int sc[8][1024];
    __shared__ int stot[8];
    int cnt[8] = {0, 0, 0, 0, 0, 0, 0, 0};
    int s0 = t * C, s1 = min(s0 + C, slots);
    for (int s = s0; s < s1; s++) {
        int tok = s >> 1;
        int2 ti = g_ti[tok];
        int e = (s & 1) ? ti.y : ti.x;
        cnt[e]++;
    }
    #pragma unroll
    for (int e = 0; e < 8; e++) sc[e][t] = cnt[e];
    __syncthreads();
    if (t < 8) {
        int run = 0;
        for (int i = 0; i < T; i++) { int v = sc[t][i]; sc[t][i] = run; run += v; }
        stot[t] = run;
        g_cnt[t] = min(run, cap);
    }
    __syncthreads();
    int pos[8];
    #pragma unroll
    for (int e = 0; e < 8; e++) pos[e] = sc[e][t];
    for (int s = s0; s < s1; s++) {
        int tok = s >> 1;
        int k = s & 1;
        int2 ti = g_ti[tok];
        float2 tw = g_tw[tok];
        int e = k ? ti.y : ti.x;
        float w = k ? tw.y : tw.x;
        int p = pos[e]++;
        bool keep = p < cap;
        int slot = e * cap + p;
        if (keep) g_rowidx[slot] = tok;
        g_slot[s] = keep ? slot : 0;
        g_wk[s]   = keep ? w : 0.0f;
    }
    // pad rows [cnt, cap) with -1 so GEMM1 treats them as zero rows
    for (int e = 0; e < 8; e++) {
        int c = min(stot[e], cap);
        for (int p = c + t; p < cap; p += T) g_rowidx[e * cap + p] = -1;
    }
}

// ---------------- GEMM1: H = gelu(gather(X) @ W1[e] + b1[e]) ----------------
// 128x128 tile, BK=16, 256 threads, 8x8/thread via fma.rn.f32x2
__global__ __launch_bounds__(256, 2)
void gemm1_kernel(const float* __restrict__ x, const float* __restrict__ W1,
                  const float* __restrict__ b1, int cap, int tpe) {
    int e = blockIdx.y / tpe, mt = blockIdx.y % tpe;
    int cnt = g_cnt[e];
    int row0 = mt * 128;
    if (row0 >= cnt) return;
    int n0 = blockIdx.x * 128;
    const float* B = W1 + (size_t)e * DMODEL * DFF;

    __shared__ float As[16][132];
    __shared__ float Bs[16][128];

    int tid = threadIdx.x;
    int arow = tid >> 2;       // 0..63
    int akq  = tid & 3;
    int r0 = row0 + arow, r1 = row0 + arow + 64;
    int tok0 = (r0 < cap) ? g_rowidx[e * cap + r0] : -1;
    int tok1 = (r1 < cap) ? g_rowidx[e * cap + r1] : -1;
    int bk = tid >> 5;         // 0..7
    int bn = (tid & 31) * 4;
    const float* bp = B + n0 + bn;
    int ty = tid >> 4, tx = tid & 15;

    ull acc[8][4];
    #pragma unroll
    for (int i = 0; i < 8; i++)
        #pragma unroll
        for (int j = 0; j < 4; j++) acc[i][j] = 0ull;

    for (int k0 = 0; k0 < DMODEL; k0 += 16) {
        float4 a0 = make_float4(0, 0, 0, 0), a1 = make_float4(0, 0, 0, 0);
        if (tok0 >= 0) a0 = *(const float4*)(x + (size_t)tok0 * DMODEL + k0 + akq * 4);
        if (tok1 >= 0) a1 = *(const float4*)(x + (size_t)tok1 * DMODEL + k0 + akq * 4);
        float4 bt0 = *(const float4*)(bp + (size_t)(k0 + bk) * DFF);
        float4 bt1 = *(const float4*)(bp + (size_t)(k0 + bk + 8) * DFF);
        __syncthreads();
        As[akq * 4 + 0][arow] = a0.x; As[akq * 4 + 1][arow] = a0.y;
        As[akq * 4 + 2][arow] = a0.z; As[akq * 4 + 3][arow] = a0.w;
        As[akq * 4 + 0][arow + 64] = a1.x; As[akq * 4 + 1][arow + 64] = a1.y;
        As[akq * 4 + 2][arow + 64] = a1.z; As[akq * 4 + 3][arow + 64] = a1.w;
        *(float4*)&Bs[bk][bn]     = bt0;
        *(float4*)&Bs[bk + 8][bn] = bt1;
        __syncthreads();
        #pragma unroll
        for (int kk = 0; kk < 16; kk++) {
            float4 af0 = *(const float4*)&As[kk][ty * 8];
            float4 af1 = *(const float4*)&As[kk][ty * 8 + 4];
            const ull* bq = (const ull*)&Bs[kk][tx * 8];
            ull b0 = bq[0], b1v = bq[1], b2v = bq[2], b3v = bq[3];
            float av[8] = {af0.x, af0.y, af0.z, af0.w, af1.x, af1.y, af1.z, af1.w};
            #pragma unroll
            for (int i = 0; i < 8; i++) {
                ull ad = dupf(av[i]);
                acc[i][0] = ffma2(ad, b0,  acc[i][0]);
                acc[i][1] = ffma2(ad, b1v, acc[i][1]);
                acc[i][2] = ffma2(ad, b2v, acc[i][2]);
                acc[i][3] = ffma2(ad, b3v, acc[i][3]);
            }
        }
    }

    const float* b1e = b1 + (size_t)e * DFF + n0 + tx * 8;
    float4 bv0 = *(const float4*)(b1e);
    float4 bv1 = *(const float4*)(b1e + 4);
    float bias[8] = {bv0.x, bv0.y, bv0.z, bv0.w, bv1.x, bv1.y, bv1.z, bv1.w};
    #pragma unroll
    for (int i = 0; i < 8; i++) {
        int r = row0 + ty * 8 + i;
        if (r >= cap) continue;
        float* hp = g_H + (size_t)(e * cap + r) * DFF + n0 + tx * 8;
        float o[8];
        #pragma unroll
        for (int j = 0; j < 4; j++) {
            float2 v = unpk(acc[i][j]);
            o[2 * j]     = gelu_exact(v.x + bias[2 * j]);
            o[2 * j + 1] = gelu_exact(v.y + bias[2 * j + 1]);
        }
        *(float4*)hp       = make_float4(o[0], o[1], o[2], o[3]);
        *(float4*)(hp + 4) = make_float4(o[4], o[5], o[6], o[7]);
    }
}

// ---------------- GEMM2: EO = H @ W2[e] + b2[e] ----------------
__global__ __launch_bounds__(256, 2)
void gemm2_kernel(const float* __restrict__ W2, const float* __restrict__ b2,
                  int cap, int tpe) {
    int e = blockIdx.y / tpe, mt = blockIdx.y % tpe;
    int cnt = g_cnt[e];
    int row0 = mt * 128;
    if (row0 >= cnt) return;
    int n0 = blockIdx.x * 128;
    const float* B = W2 + (size_t)e * DFF * DMODEL;

    __shared__ float As[16][132];
    __shared__ float Bs[16][128];

    int tid = threadIdx.x;
    int arow = tid >> 2;
    int akq  = tid & 3;
    int r0 = row0 + arow, r1 = row0 + arow + 64;
    bool v0 = (r0 < cap), v1 = (r1 < cap);
    const float* ap0 = g_H + (size_t)(e * cap + (v0 ? r0 : 0)) * DFF + akq * 4;
    const float* ap1 = g_H + (size_t)(e * cap + (v1 ? r1 : 0)) * DFF + akq * 4;
    int bk = tid >> 5;
    int bn = (tid & 31) * 4;
    const float* bp = B + n0 + bn;
    int ty = tid >> 4, tx = tid & 15;

    ull acc[8][4];
    #pragma unroll
    for (int i = 0; i < 8; i++)
        #pragma unroll
        for (int j = 0; j < 4; j++) acc[i][j] = 0ull;

    for (int k0 = 0; k0 < DFF; k0 += 16) {
        float4 a0 = *(const float4*)(ap0 + k0);
        float4 a1 = *(const float4*)(ap1 + k0);
        float4 bt0 = *(const float4*)(bp + (size_t)(k0 + bk) * DMODEL);
        float4 bt1 = *(const float4*)(bp + (size_t)(k0 + bk + 8) * DMODEL);
        __syncthreads();
        As[akq * 4 + 0][arow] = a0.x; As[akq * 4 + 1][arow] = a0.y;
        As[akq * 4 + 2][arow] = a0.z; As[akq * 4 + 3][arow] = a0.w;
        As[akq * 4 + 0][arow + 64] = a1.x; As[akq * 4 + 1][arow + 64] = a1.y;
        As[akq * 4 + 2][arow + 64] = a1.z; As[akq * 4 + 3][arow + 64] = a1.w;
        *(float4*)&Bs[bk][bn]     = bt0;
        *(float4*)&Bs[bk + 8][bn] = bt1;
        __syncthreads();
        #pragma unroll
        for (int kk = 0; kk < 16; kk++) {
            float4 af0 = *(const float4*)&As[kk][ty * 8];
            float4 af1 = *(const float4*)&As[kk][ty * 8 + 4];
            const ull* bq = (const ull*)&Bs[kk][tx * 8];
            ull b0 = bq[0], b1v = bq[1], b2v = bq[2], b3v = bq[3];
            float av[8] = {af0.x, af0.y, af0.z, af0.w, af1.x, af1.y, af1.z, af1.w};
            #pragma unroll
            for (int i = 0; i < 8; i++) {
                ull ad = dupf(av[i]);
                acc[i][0] = ffma2(ad, b0,  acc[i][0]);
                acc[i][1] = ffma2(ad, b1v, acc[i][1]);
                acc[i][2] = ffma2(ad, b2v, acc[i][2]);
                acc[i][3] = ffma2(ad, b3v, acc[i][3]);
            }
        }
    }

    const float* b2e = b2 + (size_t)e * DMODEL + n0 + tx * 8;
    float4 bv0 = *(const float4*)(b2e);
    float4 bv1 = *(const float4*)(b2e + 4);
    float bias[8] = {bv0.x, bv0.y, bv0.z, bv0.w, bv1.x, bv1.y, bv1.z, bv1.w};
    #pragma unroll
    for (int i = 0; i < 8; i++) {
        int r = row0 + ty * 8 + i;
        if (r >= cap) continue;
        float* op = g_EO + (size_t)(e * cap + r) * DMODEL + n0 + tx * 8;
        float o[8];
        #pragma unroll
        for (int j = 0; j < 4; j++) {
            float2 v = unpk(acc[i][j]);
            o[2 * j]     = v.x + bias[2 * j];
            o[2 * j + 1] = v.y + bias[2 * j + 1];
        }
        *(float4*)op       = make_float4(o[0], o[1], o[2], o[3]);
        *(float4*)(op + 4) = make_float4(o[4], o[5], o[6], o[7]);
    }
}

// ---------------- combine: y[tok] = sum_k w_norm * EO[slot_k] ----------------
__global__ void combine_kernel(float* __restrict__ out, int N) {
    int gid = blockIdx.x * blockDim.x + threadIdx.x;
    if (gid >= N * (DMODEL / 4)) return;
    int tok = gid >> 7;
    int j = gid & 127;
    int s0 = g_slot[2 * tok], s1 = g_slot[2 * tok + 1];
    float w0 = g_wk[2 * tok], w1 = g_wk[2 * tok + 1];
    float inv = 1.0f / (w0 + w1 + 1e-9f);
    w0 *= inv; w1 *= inv;
    const float4* e0 = (const float4*)(g_EO + (size_t)s0 * DMODEL);
    const float4* e1 = (const float4*)(g_EO + (size_t)s1 * DMODEL);
    float4 a = e0[j], b = e1[j];
    float4 r;
    r.x = w0 * a.x + w1 * b.x;
    r.y = w0 * a.y + w1 * b.y;
    r.z = w0 * a.z + w1 * b.z;
    r.w = w0 * a.w + w1 * b.w;
    ((float4*)out)[gid] = r;
}

// ---------------- launch ----------------
extern "C" void kernel_launch(void* const* d_in, const int* in_sizes, int n_in,
                              void* d_out, int out_size) {
    const float* x  = (const float*)d_in[0];
    const float* Wr = (const float*)d_in[1];
    const float* br = (const float*)d_in[2];
    const float* W1 = (const float*)d_in[3];
    const float* b1 = (const float*)d_in[4];
    const float* W2 = (const float*)d_in[5];
    const float* b2 = (const float*)d_in[6];
    float* out = (float*)d_out;

    int N = in_sizes[0] / DMODEL;           // 32768
    if (N > NMAX) N = NMAX;
    int cap = (5 * N + 15) / 16;            // ceil(1.25*N*K/E) = ceil(5N/16) = 10240
    if (cap > CAPMAX) cap = CAPMAX;
    int tpe = (cap + 127) / 128;            // 80

    router_kernel<<<(N * 32 + 255) / 256, 256>>>(x, Wr, br, N);
    dispatch_kernel<<<1, 1024>>>(N, cap);
    dim3 g1(DFF / 128, NEXP * tpe);
    gemm1_kernel<<<g1, 256>>>(x, W1, b1, cap, tpe);
    dim3 g2(DMODEL / 128, NEXP * tpe);
    gemm2_kernel<<<g2, 256>>>(W2, b2, cap, tpe);
    combine_kernel<<<(N * (DMODEL / 4) + 255) / 256, 256>>>(out, N);
}

// round 3
// speedup vs baseline: 3.2424x; 3.2424x over previous
#include <cuda_runtime.h>
#include <cuda_bf16.h>
#include <cstdint>

#define DMODEL 512
#define DFF 2048
#define NEXP 8
#define TOPK 2
#define NMAX 32768
#define CAPMAX 10240
#define EROWS (NEXP * CAPMAX)

typedef unsigned long long ull;

// ---------------- scratch ----------------
__device__ __align__(1024) __nv_bfloat16 g_A1h[(size_t)EROWS * DMODEL];
__device__ __align__(1024) __nv_bfloat16 g_A1l[(size_t)EROWS * DMODEL];
__device__ __align__(1024) __nv_bfloat16 g_Hh [(size_t)EROWS * DFF];
__device__ __align__(1024) __nv_bfloat16 g_Hl [(size_t)EROWS * DFF];
__device__ __align__(1024) __nv_bfloat16 g_W1h[(size_t)NEXP * DFF * DMODEL];   // [e][n][k]
__device__ __align__(1024) __nv_bfloat16 g_W1l[(size_t)NEXP * DFF * DMODEL];
__device__ __align__(1024) __nv_bfloat16 g_W2h[(size_t)NEXP * DMODEL * DFF];   // [e][n][k]
__device__ __align__(1024) __nv_bfloat16 g_W2l[(size_t)NEXP * DMODEL * DFF];
__device__ __align__(1024) float g_EO[(size_t)EROWS * DMODEL];
__device__ int    g_rowidx[EROWS];
__device__ int    g_slot[NMAX * TOPK];
__device__ float  g_wk  [NMAX * TOPK];
__device__ int2   g_ti[NMAX];
__device__ float2 g_tw[NMAX];
__device__ int    g_cnt[NEXP];

// ---------------- helpers ----------------
__device__ __forceinline__ uint32_t s2u(const void* p) {
    uint32_t a;
    asm("{ .reg .u64 t; cvta.to.shared.u64 t, %1; cvt.u32.u64 %0, t; }" : "=r"(a) : "l"(p));
    return a;
}
__device__ __forceinline__ float gelu_exact(float v) {
    return 0.5f * v * (1.0f + erff(v * 0.7071067811865476f));
}
__device__ __forceinline__ unsigned short bfu(__nv_bfloat16 h) { return __bfloat16_as_ushort(h); }

__device__ __forceinline__ void cp16(uint32_t s, const void* g) {
    asm volatile("cp.async.cg.shared.global [%0], [%1], 16;" :: "r"(s), "l"(g));
}
__device__ __forceinline__ void cp_commit() { asm volatile("cp.async.commit_group;"); }
template<int N> __device__ __forceinline__ void cp_wait() {
    asm volatile("cp.async.wait_group %0;" :: "n"(N));
}
__device__ __forceinline__ void ldm_x4(uint32_t* r, uint32_t a) {
    asm volatile("ldmatrix.sync.aligned.m8n8.x4.shared.b16 {%0,%1,%2,%3}, [%4];"
                 : "=r"(r[0]), "=r"(r[1]), "=r"(r[2]), "=r"(r[3]) : "r"(a));
}
__device__ __forceinline__ void ldm_x2(uint32_t* r, uint32_t a) {
    asm volatile("ldmatrix.sync.aligned.m8n8.x2.shared.b16 {%0,%1}, [%2];"
                 : "=r"(r[0]), "=r"(r[1]) : "r"(a));
}
__device__ __forceinline__ void mma16816(float* c, const uint32_t* a, const uint32_t* b) {
    asm volatile(
        "mma.sync.aligned.m16n8k16.row.col.f32.bf16.bf16.f32 "
        "{%0,%1,%2,%3}, {%4,%5,%6,%7}, {%8,%9}, {%0,%1,%2,%3};"
        : "+f"(c[0]), "+f"(c[1]), "+f"(c[2]), "+f"(c[3])
        : "r"(a[0]), "r"(a[1]), "r"(a[2]), "r"(a[3]), "r"(b[0]), "r"(b[1]));
}

// ---------------- router ----------------
__global__ void router_kernel(const float* __restrict__ x,
                              const float* __restrict__ Wr,
                              const float* __restrict__ br, int N) {
    int warp = (blockIdx.x * blockDim.x + threadIdx.x) >> 5;
    int lane = threadIdx.x & 31;
    if (warp >= N) return;
    const float* xr = x + (size_t)warp * DMODEL;
    float acc[8] = {0, 0, 0, 0, 0, 0, 0, 0};
    for (int d = lane; d < DMODEL; d += 32) {
        float xv = xr[d];
        float4 w0 = *(const float4*)(Wr + (size_t)d * 8);
        float4 w1 = *(const float4*)(Wr + (size_t)d * 8 + 4);
        acc[0] += xv * w0.x; acc[1] += xv * w0.y;
        acc[2] += xv * w0.z; acc[3] += xv * w0.w;
        acc[4] += xv * w1.x; acc[5] += xv * w1.y;
        acc[6] += xv * w1.z; acc[7] += xv * w1.w;
    }
    #pragma unroll
    for (int o = 16; o; o >>= 1)
        #pragma unroll
        for (int e = 0; e < 8; e++)
            acc[e] += __shfl_xor_sync(0xFFFFFFFFu, acc[e], o);
    if (lane == 0) {
        float l[8], p[8];
        float m = -1e30f;
        #pragma unroll
        for (int e = 0; e < 8; e++) { l[e] = acc[e] + br[e]; m = fmaxf(m, l[e]); }
        float s = 0.f;
        #pragma unroll
        for (int e = 0; e < 8; e++) { p[e] = expf(l[e] - m); s += p[e]; }
        float inv = 1.0f / s;
        #pragma unroll
        for (int e = 0; e < 8; e++) p[e] *= inv;
        int i1 = 0; float p1 = p[0];
        #pragma unroll
        for (int e = 1; e < 8; e++) if (p[e] > p1) { p1 = p[e]; i1 = e; }
        int i2 = -1; float p2 = -1.0f;
        #pragma unroll
        for (int e = 0; e < 8; e++) if (e != i1 && p[e] > p2) { p2 = p[e]; i2 = e; }
        float den = p1 + p2 + 1e-9f;
        g_ti[warp] = make_int2(i1, i2);
        g_tw[warp] = make_float2(p1 / den, p2 / den);
    }
}

// ---------------- dispatch ----------------
__global__ void dispatch_kernel(int N, int cap) {
    const int T = 1024;
    int t = threadIdx.x;
    int slots = N * TOPK;
    int C = (slots + T - 1) / T;
    __shared__ int sc[8][1024];
    __shared__ int stot[8];
    int cnt[8] = {0, 0, 0, 0, 0, 0, 0, 0};
    int s0 = t * C, s1 = min(s0 + C, slots);
    for (int s = s0; s < s1; s++) {
        int2 ti = g_ti[s >> 1];
        cnt[(s & 1) ? ti.y : ti.x]++;
    }
    #pragma unroll
    for (int e = 0; e < 8; e++) sc[e][t] = cnt[e];
    __syncthreads();
    if (t < 8) {
        int run = 0;
        for (int i = 0; i < T; i++) { int v = sc[t][i]; sc[t][i] = run; run += v; }
        stot[t] = run;
        g_cnt[t] = min(run, cap);
    }
    __syncthreads();
    int pos[8];
    #pragma unroll
    for (int e = 0; e < 8; e++) pos[e] = sc[e][t];
    for (int s = s0; s < s1; s++) {
        int tok = s >> 1, k = s & 1;
        int2 ti = g_ti[tok];
        float2 tw = g_tw[tok];
        int e = k ? ti.y : ti.x;
        float w = k ? tw.y : tw.x;
        int p = pos[e]++;
        bool keep = p < cap;
        int slot = e * cap + p;
        if (keep) g_rowidx[slot] = tok;
        g_slot[s] = keep ? slot : 0;
        g_wk[s]   = keep ? w : 0.0f;
    }
    for (int e = 0; e < 8; e++) {
        int c = min(stot[e], cap);
        for (int p = c + t; p < cap; p += T) g_rowidx[e * cap + p] = -1;
    }
}

// ---------------- weight convert+transpose ----------------
__global__ void wconvert_kernel(const float* __restrict__ src,
                                __nv_bfloat16* __restrict__ dh,
                                __nv_bfloat16* __restrict__ dl, int R, int C) {
    int e = blockIdx.z;
    int c0 = blockIdx.x * 32, r0 = blockIdx.y * 32;
    __shared__ float t[32][33];
    int tx = threadIdx.x & 31, ty = threadIdx.x >> 5;
    const float* s = src + (size_t)e * R * C;
    #pragma unroll
    for (int i = 0; i < 4; i++)
        t[ty + i * 8][tx] = s[(size_t)(r0 + ty + i * 8) * C + c0 + tx];
    __syncthreads();
    size_t ob = (size_t)e * C * R;
    #pragma unroll
    for (int i = 0; i < 4; i++) {
        int c = c0 + ty + i * 8;
        float v = t[tx][ty + i * 8];
        __nv_bfloat16 hb = __float2bfloat16(v);
        __nv_bfloat16 lb = __float2bfloat16(v - __bfloat162float(hb));
        size_t o = ob + (size_t)c * R + r0 + tx;
        dh[o] = hb; dl[o] = lb;
    }
}

// ---------------- gather ----------------
__global__ void gather_kernel(const float* __restrict__ x,
                              __nv_bfloat16* __restrict__ Ah,
                              __nv_bfloat16* __restrict__ Al) {
    int gid = blockIdx.x * 256 + threadIdx.x;
    int row = gid >> 7, j = gid & 127;
    int tok = g_rowidx[row];
    float4 v = make_float4(0, 0, 0, 0);
    if (tok >= 0) v = ((const float4*)(x + (size_t)tok * DMODEL))[j];
    __nv_bfloat16 h0 = __float2bfloat16(v.x), h1 = __float2bfloat16(v.y);
    __nv_bfloat16 h2 = __float2bfloat16(v.z), h3 = __float2bfloat16(v.w);
    __nv_bfloat16 l0 = __float2bfloat16(v.x - __bfloat162float(h0));
    __nv_bfloat16 l1 = __float2bfloat16(v.y - __bfloat162float(h1));
    __nv_bfloat16 l2 = __float2bfloat16(v.z - __bfloat162float(h2));
    __nv_bfloat16 l3 = __float2bfloat16(v.w - __bfloat162float(h3));
    uint2 ph, pl;
    ph.x = (uint32_t)bfu(h0) | ((uint32_t)bfu(h1) << 16);
    ph.y = (uint32_t)bfu(h2) | ((uint32_t)bfu(h3) << 16);
    pl.x = (uint32_t)bfu(l0) | ((uint32_t)bfu(l1) << 16);
    pl.y = (uint32_t)bfu(l2) | ((uint32_t)bfu(l3) << 16);
    ((uint2*)(Ah + (size_t)row * DMODEL))[j] = ph;
    ((uint2*)(Al + (size_t)row * DMODEL))[j] = pl;
}

// ---------------- mma.sync GEMM: tile 128x256, K-stage 32, 3-stage cp.async ----------------
// smem row stride 80B (20 words): conflict-free ldmatrix phases.
#define RSTR 80
#define A_PL (128 * RSTR)          // one A plane bytes (6->10240)
#define B_PL (256 * RSTR)
#define ST_AH 0
#define ST_AL (A_PL)
#define ST_BH (2 * A_PL)
#define ST_BL (2 * A_PL + B_PL)
#define ST_SZ (2 * A_PL + 2 * B_PL)     // 61440
#define NST 3
#define SMEM_TOT (NST * ST_SZ)          // 184320

template<int KTOT, int NF, bool G1>
__global__ void __launch_bounds__(256, 1)
gemm_mma(const __nv_bfloat16* __restrict__ Ah, const __nv_bfloat16* __restrict__ Al,
         const __nv_bfloat16* __restrict__ Bh, const __nv_bfloat16* __restrict__ Bl,
         const float* __restrict__ bias,
         __nv_bfloat16* __restrict__ Oh, __nv_bfloat16* __restrict__ Ol,
         float* __restrict__ Of, int cap, int tpe) {
    int e = blockIdx.y / tpe, mt = blockIdx.y % tpe;
    if (mt * 128 >= g_cnt[e]) return;
    const int row0 = mt * 128;
    const int n0 = blockIdx.x * 256;
    extern __shared__ char sm[];
    const uint32_t sb = s2u(sm);
    const int tid = threadIdx.x;
    const int wid = tid >> 5, lane = tid & 31;
    const int wm = wid >> 2, wn = wid & 3;          // warp tile: rows wm*64, cols wn*64

    const size_t arow0 = (size_t)e * cap + row0;
    const __nv_bfloat16* pAh = Ah + arow0 * KTOT;
    const __nv_bfloat16* pAl = Al + arow0 * KTOT;
    const size_t brow0 = (size_t)e * NF + n0;
    const __nv_bfloat16* pBh = Bh + brow0 * KTOT;
    const __nv_bfloat16* pBl = Bl + brow0 * KTOT;

    // load decomposition (per thread per stage): A 4 chunks, B 8 chunks of 16B
    int aplane = tid >= 128 ? 1 : 0;     // idx = j*256+tid over 1024: plane=idx>=512
    // simpler: recompute inside lambda from linear idx

    auto load_stage = [&](int buf, int kbase) {
        uint32_t sbase = sb + buf * ST_SZ;
        #pragma unroll
        for (int j = 0; j < 4; j++) {               // A: 1024 chunks
            int idx = j * 256 + tid;
            int pl = idx >> 9;                      // 0:hi 1:lo
            int rem = idx & 511;
            int r = rem >> 2, c = rem & 3;
            const __nv_bfloat16* g = (pl ? pAl : pAh) + (size_t)r * KTOT + kbase + c * 8;
            cp16(sbase + (pl ? ST_AL : ST_AH) + r * RSTR + c * 16, g);
        }
        #pragma unroll
        for (int j = 0; j < 8; j++) {               // B: 2048 chunks
            int idx = j * 256 + tid;
            int pl = idx >> 10;
            int rem = idx & 1023;
            int r = rem >> 2, c = rem & 3;
            const __nv_bfloat16* g = (pl ? pBl : pBh) + (size_t)r * KTOT + kbase + c * 8;
            cp16(sbase + (pl ? ST_BL : ST_BH) + r * RSTR + c * 16, g);
        }
    };

    float acc[4][8][4];
    #pragma unroll
    for (int i = 0; i < 4; i++)
        #pragma unroll
        for (int j = 0; j < 8; j++)
            #pragma unroll
            for (int q = 0; q < 4; q++) acc[i][j][q] = 0.f;

    // per-lane ldmatrix address pieces
    const uint32_t aRow = (uint32_t)(wm * 64 + (lane & 15)) * RSTR + (lane >> 4) * 16;
    const uint32_t bRow = (uint32_t)(wn * 64 + (lane & 7)) * RSTR + ((lane >> 3) & 1) * 16;

    const int NK = KTOT / 32;
    load_stage(0, 0); cp_commit();
    load_stage(1, 32); cp_commit();

    for (int s = 0; s < NK; s++) {
        cp_wait<1>();
        __syncthreads();
        if (s + 2 < NK) load_stage((s + 2) % NST, (s + 2) * 32);
        cp_commit();

        uint32_t sbase = sb + (s % NST) * ST_SZ;
        #pragma unroll
        for (int kk = 0; kk < 2; kk++) {
            uint32_t koff = kk * 32;                 // 2 chunks of 16B per kstep
            uint32_t ah[4][4], al[4][4];
            #pragma unroll
            for (int mi = 0; mi < 4; mi++) {
                uint32_t base = sbase + aRow + mi * (16 * RSTR) + koff;
                ldm_x4(ah[mi], base + ST_AH);
                ldm_x4(al[mi], base + ST_AL);
            }
            #pragma unroll
            for (int ni = 0; ni < 8; ni++) {
                uint32_t bb = sbase + bRow + ni * (8 * RSTR) + koff;
                uint32_t bh[2], bl[2];
                ldm_x2(bh, bb + ST_BH);
                ldm_x2(bl, bb + ST_BL);
                #pragma unroll
                for (int mi = 0; mi < 4; mi++) {
                    mma16816(acc[mi][ni], ah[mi], bh);
                    mma16816(acc[mi][ni], ah[mi], bl);
                    mma16816(acc[mi][ni], al[mi], bh);
                }
            }
        }
        __syncthreads();
    }

    // ---------------- epilogue ----------------
    const int colbase = n0 + wn * 64 + (lane & 3) * 2;
    const int rowbase = wm * 64 + (lane >> 2);
    #pragma unroll
    for (int mi = 0; mi < 4; mi++) {
        #pragma unroll
        for (int half = 0; half < 2; half++) {
            int r = rowbase + mi * 16 + half * 8;
            size_t grow = arow0 + r;
            #pragma unroll
            for (int ni = 0; ni < 8; ni++) {
                int col = colbase + ni * 8;
                float v0 = acc[mi][ni][half * 2 + 0];
                float v1 = acc[mi][ni][half * 2 + 1];
                float2 bv = *(const float2*)(bias + (size_t)e * NF + col);
                v0 += bv.x; v1 += bv.y;
                if (G1) {
                    float gv0 = gelu_exact(v0), gv1 = gelu_exact(v1);
                    __nv_bfloat16 h0 = __float2bfloat16(gv0), h1 = __float2bfloat16(gv1);
                    __nv_bfloat16 l0 = __float2bfloat16(gv0 - __bfloat162float(h0));
                    __nv_bfloat16 l1 = __float2bfloat16(gv1 - __bfloat162float(h1));
                    *(uint32_t*)(Oh + grow * NF + col) =
                        (uint32_t)bfu(h0) | ((uint32_t)bfu(h1) << 16);
                    *(uint32_t*)(Ol + grow * NF + col) =
                        (uint32_t)bfu(l0) | ((uint32_t)bfu(l1) << 16);
                } else {
                    *(float2*)(Of + grow * NF + col) = make_float2(v0, v1);
                }
            }
        }
    }
}

// ---------------- combine ----------------
__global__ void combine_kernel(float* __restrict__ out, int N) {
    int gid = blockIdx.x * blockDim.x + threadIdx.x;
    if (gid >= N * (DMODEL / 4)) return;
    int tok = gid >> 7;
    int j = gid & 127;
    int s0 = g_slot[2 * tok], s1 = g_slot[2 * tok + 1];
    float w0 = g_wk[2 * tok], w1 = g_wk[2 * tok + 1];
    float inv = 1.0f / (w0 + w1 + 1e-9f);
    w0 *= inv; w1 *= inv;
    const float4* e0 = (const float4*)(g_EO + (size_t)s0 * DMODEL);
    const float4* e1 = (const float4*)(g_EO + (size_t)s1 * DMODEL);
    float4 a = e0[j], b = e1[j];
    float4 r;
    r.x = w0 * a.x + w1 * b.x;
    r.y = w0 * a.y + w1 * b.y;
    r.z = w0 * a.z + w1 * b.z;
    r.w = w0 * a.w + w1 * b.w;
    ((float4*)out)[gid] = r;
}

// ---------------- launch ----------------
extern "C" void kernel_launch(void* const* d_in, const int* in_sizes, int n_in,
                              void* d_out, int out_size) {
    const float* x  = (const float*)d_in[0];
    const float* Wr = (const float*)d_in[1];
    const float* br = (const float*)d_in[2];
    const float* W1 = (const float*)d_in[3];
    const float* b1 = (const float*)d_in[4];
    const float* W2 = (const float*)d_in[5];
    const float* b2 = (const float*)d_in[6];
    float* out = (float*)d_out;

    int N = in_sizes[0] / DMODEL;
    if (N > NMAX) N = NMAX;
    int cap = (5 * N + 15) / 16;
    if (cap > CAPMAX) cap = CAPMAX;
    int tpe = (cap + 127) / 128;

    void *a1h, *a1l, *hh, *hl, *w1h, *w1l, *w2h, *w2l, *eo;
    cudaGetSymbolAddress(&a1h, g_A1h); cudaGetSymbolAddress(&a1l, g_A1l);
    cudaGetSymbolAddress(&hh,  g_Hh);  cudaGetSymbolAddress(&hl,  g_Hl);
    cudaGetSymbolAddress(&w1h, g_W1h); cudaGetSymbolAddress(&w1l, g_W1l);
    cudaGetSymbolAddress(&w2h, g_W2h); cudaGetSymbolAddress(&w2l, g_W2l);
    cudaGetSymbolAddress(&eo,  g_EO);

    cudaFuncSetAttribute(gemm_mma<DMODEL, DFF, true>,
                         cudaFuncAttributeMaxDynamicSharedMemorySize, SMEM_TOT);
    cudaFuncSetAttribute(gemm_mma<DFF, DMODEL, false>,
                         cudaFuncAttributeMaxDynamicSharedMemorySize, SMEM_TOT);

    router_kernel<<<(N * 32 + 255) / 256, 256>>>(x, Wr, br, N);
    dispatch_kernel<<<1, 1024>>>(N, cap);
    wconvert_kernel<<<dim3(DFF / 32, DMODEL / 32, NEXP), 256>>>(
        W1, (__nv_bfloat16*)w1h, (__nv_bfloat16*)w1l, DMODEL, DFF);
    wconvert_kernel<<<dim3(DMODEL / 32, DFF / 32, NEXP), 256>>>(
        W2, (__nv_bfloat16*)w2h, (__nv_bfloat16*)w2l, DFF, DMODEL);
    gather_kernel<<<(NEXP * cap * 128) / 256, 256>>>(
        x, (__nv_bfloat16*)a1h, (__nv_bfloat16*)a1l);

    dim3 g1(DFF / 256, NEXP * tpe);
    gemm_mma<DMODEL, DFF, true><<<g1, 256, SMEM_TOT>>>(
        (const __nv_bfloat16*)a1h, (const __nv_bfloat16*)a1l,
        (const __nv_bfloat16*)w1h, (const __nv_bfloat16*)w1l,
        b1, (__nv_bfloat16*)hh, (__nv_bfloat16*)hl, nullptr, cap, tpe);

    dim3 g2(DMODEL / 256, NEXP * tpe);
    gemm_mma<DFF, DMODEL, false><<<g2, 256, SMEM_TOT>>>(
        (const __nv_bfloat16*)hh, (const __nv_bfloat16*)hl,
        (const __nv_bfloat16*)w2h, (const __nv_bfloat16*)w2l,
        b2, nullptr, nullptr, (float*)eo, cap, tpe);

    combine_kernel<<<(N * (DMODEL / 4) + 255) / 256, 256>>>(out, N);
}

// round 4
// speedup vs baseline: 3.3155x; 1.0225x over previous
#include <cuda_runtime.h>
#include <cuda_bf16.h>
#include <cstdint>

#define DMODEL 512
#define DFF 2048
#define NEXP 8
#define TOPK 2
#define NMAX 32768
#define CAPMAX 10240
#define EROWS (NEXP * CAPMAX)

typedef unsigned long long ull;

// ---------------- scratch ----------------
__device__ __align__(1024) __nv_bfloat16 g_A1h[(size_t)EROWS * DMODEL];
__device__ __align__(1024) __nv_bfloat16 g_A1l[(size_t)EROWS * DMODEL];
__device__ __align__(1024) __nv_bfloat16 g_Hh [(size_t)EROWS * DFF];
__device__ __align__(1024) __nv_bfloat16 g_Hl [(size_t)EROWS * DFF];
__device__ __align__(1024) __nv_bfloat16 g_W1h[(size_t)NEXP * DFF * DMODEL];   // [e][n][k]
__device__ __align__(1024) __nv_bfloat16 g_W1l[(size_t)NEXP * DFF * DMODEL];
__device__ __align__(1024) __nv_bfloat16 g_W2h[(size_t)NEXP * DMODEL * DFF];   // [e][n][k]
__device__ __align__(1024) __nv_bfloat16 g_W2l[(size_t)NEXP * DMODEL * DFF];
__device__ __align__(1024) float g_EO[(size_t)EROWS * DMODEL];
__device__ int    g_rowidx[EROWS];
__device__ int    g_slot[NMAX * TOPK];
__device__ float  g_wk  [NMAX * TOPK];
__device__ int2   g_ti[NMAX];
__device__ float2 g_tw[NMAX];
__device__ int    g_cnt[NEXP];

// ---------------- helpers ----------------
__device__ __forceinline__ uint32_t s2u(const void* p) {
    uint32_t a;
    asm("{ .reg .u64 t; cvta.to.shared.u64 t, %1; cvt.u32.u64 %0, t; }" : "=r"(a) : "l"(p));
    return a;
}
__device__ __forceinline__ float gelu_exact(float v) {
    return 0.5f * v * (1.0f + erff(v * 0.7071067811865476f));
}
// hi plane: truncated top-16 bits of two floats packed as bf16x2
__device__ __forceinline__ uint32_t prmt_hi(float a, float b) {
    uint32_t r;
    asm("prmt.b32 %0, %1, %2, 0x7632;" : "=r"(r)
        : "r"(__float_as_uint(a)), "r"(__float_as_uint(b)));
    return r;
}
__device__ __forceinline__ float truncbf(float v) {
    return __uint_as_float(__float_as_uint(v) & 0xFFFF0000u);
}
// pack {lo16=x, hi16=y} as rn bf16x2
__device__ __forceinline__ uint32_t cvt_bf2(float x, float y) {
    uint32_t r;
    asm("cvt.rn.bf16x2.f32 %0, %1, %2;" : "=r"(r) : "f"(y), "f"(x));
    return r;
}

__device__ __forceinline__ void cp16(uint32_t s, const void* g) {
    asm volatile("cp.async.cg.shared.global [%0], [%1], 16;" :: "r"(s), "l"(g));
}
__device__ __forceinline__ void cp_commit() { asm volatile("cp.async.commit_group;"); }
template<int N> __device__ __forceinline__ void cp_wait() {
    asm volatile("cp.async.wait_group %0;" :: "n"(N));
}
__device__ __forceinline__ void ldm_x4(uint32_t* r, uint32_t a) {
    asm volatile("ldmatrix.sync.aligned.m8n8.x4.shared.b16 {%0,%1,%2,%3}, [%4];"
                 : "=r"(r[0]), "=r"(r[1]), "=r"(r[2]), "=r"(r[3]) : "r"(a));
}
__device__ __forceinline__ void mma16816(float* c, const uint32_t* a, const uint32_t* b) {
    asm volatile(
        "mma.sync.aligned.m16n8k16.row.col.f32.bf16.bf16.f32 "
        "{%0,%1,%2,%3}, {%4,%5,%6,%7}, {%8,%9}, {%0,%1,%2,%3};"
        : "+f"(c[0]), "+f"(c[1]), "+f"(c[2]), "+f"(c[3])
        : "r"(a[0]), "r"(a[1]), "r"(a[2]), "r"(a[3]), "r"(b[0]), "r"(b[1]));
}

// ---------------- router ----------------
__global__ void router_kernel(const float* __restrict__ x,
                              const float* __restrict__ Wr,
                              const float* __restrict__ br, int N) {
    int warp = (blockIdx.x * blockDim.x + threadIdx.x) >> 5;
    int lane = threadIdx.x & 31;
    if (warp >= N) return;
    const float* xr = x + (size_t)warp * DMODEL;
    float acc[8] = {0, 0, 0, 0, 0, 0, 0, 0};
    for (int d = lane; d < DMODEL; d += 32) {
        float xv = xr[d];
        float4 w0 = *(const float4*)(Wr + (size_t)d * 8);
        float4 w1 = *(const float4*)(Wr + (size_t)d * 8 + 4);
        acc[0] += xv * w0.x; acc[1] += xv * w0.y;
        acc[2] += xv * w0.z; acc[3] += xv * w0.w;
        acc[4] += xv * w1.x; acc[5] += xv * w1.y;
        acc[6] += xv * w1.z; acc[7] += xv * w1.w;
    }
    #pragma unroll
    for (int o = 16; o; o >>= 1)
        #pragma unroll
        for (int e = 0; e < 8; e++)
            acc[e] += __shfl_xor_sync(0xFFFFFFFFu, acc[e], o);
    if (lane == 0) {
        float l[8], p[8];
        float m = -1e30f;
        #pragma unroll
        for (int e = 0; e < 8; e++) { l[e] = acc[e] + br[e]; m = fmaxf(m, l[e]); }
        float s = 0.f;
        #pragma unroll
        for (int e = 0; e < 8; e++) { p[e] = expf(l[e] - m); s += p[e]; }
        float inv = 1.0f / s;
        #pragma unroll
        for (int e = 0; e < 8; e++) p[e] *= inv;
        int i1 = 0; float p1 = p[0];
        #pragma unroll
        for (int e = 1; e < 8; e++) if (p[e] > p1) { p1 = p[e]; i1 = e; }
        int i2 = -1; float p2 = -1.0f;
        #pragma unroll
        for (int e = 0; e < 8; e++) if (e != i1 && p[e] > p2) { p2 = p[e]; i2 = e; }
        float den = p1 + p2 + 1e-9f;
        g_ti[warp] = make_int2(i1, i2);
        g_tw[warp] = make_float2(p1 / den, p2 / den);
    }
}

// ---------------- dispatch ----------------
__global__ void dispatch_kernel(int N, int cap) {
    const int T = 1024;
    int t = threadIdx.x;
    int slots = N * TOPK;
    int C = (slots + T - 1) / T;
    __shared__ int sc[8][1024];
    __shared__ int stot[8];
    int cnt[8] = {0, 0, 0, 0, 0, 0, 0, 0};
    int s0 = t * C, s1 = min(s0 + C, slots);
    for (int s = s0; s < s1; s++) {
        int2 ti = g_ti[s >> 1];
        cnt[(s & 1) ? ti.y : ti.x]++;
    }
    #pragma unroll
    for (int e = 0; e < 8; e++) sc[e][t] = cnt[e];
    __syncthreads();
    if (t < 8) {
        int run = 0;
        for (int i = 0; i < T; i++) { int v = sc[t][i]; sc[t][i] = run; run += v; }
        stot[t] = run;
        g_cnt[t] = min(run, cap);
    }
    __syncthreads();
    int pos[8];
    #pragma unroll
    for (int e = 0; e < 8; e++) pos[e] = sc[e][t];
    for (int s = s0; s < s1; s++) {
        int tok = s >> 1, k = s & 1;
        int2 ti = g_ti[tok];
        float2 tw = g_tw[tok];
        int e = k ? ti.y : ti.x;
        float w = k ? tw.y : tw.x;
        int p = pos[e]++;
        bool keep = p < cap;
        int slot = e * cap + p;
        if (keep) g_rowidx[slot] = tok;
        g_slot[s] = keep ? slot : 0;
        g_wk[s]   = keep ? w : 0.0f;
    }
    for (int e = 0; e < 8; e++) {
        int c = min(stot[e], cap);
        for (int p = c + t; p < cap; p += T) g_rowidx[e * cap + p] = -1;
    }
}

// ---------------- weight convert+transpose (truncation split) ----------------
__global__ void wconvert_kernel(const float* __restrict__ src,
                                __nv_bfloat16* __restrict__ dh,
                                __nv_bfloat16* __restrict__ dl, int R, int C) {
    int e = blockIdx.z;
    int c0 = blockIdx.x * 32, r0 = blockIdx.y * 32;
    __shared__ float t[32][33];
    int tx = threadIdx.x & 31, ty = threadIdx.x >> 5;
    const float* s = src + (size_t)e * R * C;
    #pragma unroll
    for (int i = 0; i < 4; i++)
        t[ty + i * 8][tx] = s[(size_t)(r0 + ty + i * 8) * C + c0 + tx];
    __syncthreads();
    size_t ob = (size_t)e * C * R;
    #pragma unroll
    for (int i = 0; i < 4; i++) {
        int c = c0 + ty + i * 8;
        float v = t[tx][ty + i * 8];
        size_t o = ob + (size_t)c * R + r0 + tx;
        dh[o] = __ushort_as_bfloat16((unsigned short)(__float_as_uint(v) >> 16));
        dl[o] = __float2bfloat16(v - truncbf(v));
    }
}

// ---------------- gather (truncation split) ----------------
__global__ void gather_kernel(const float* __restrict__ x,
                              __nv_bfloat16* __restrict__ Ah,
                              __nv_bfloat16* __restrict__ Al) {
    int gid = blockIdx.x * 256 + threadIdx.x;
    int row = gid >> 7, j = gid & 127;
    int tok = g_rowidx[row];
    float4 v = make_float4(0, 0, 0, 0);
    if (tok >= 0) v = ((const float4*)(x + (size_t)tok * DMODEL))[j];
    uint2 ph, pl;
    ph.x = prmt_hi(v.x, v.y);
    ph.y = prmt_hi(v.z, v.w);
    pl.x = cvt_bf2(v.x - truncbf(v.x), v.y - truncbf(v.y));
    pl.y = cvt_bf2(v.z - truncbf(v.z), v.w - truncbf(v.w));
    ((uint2*)(Ah + (size_t)row * DMODEL))[j] = ph;
    ((uint2*)(Al + (size_t)row * DMODEL))[j] = pl;
}

// ---------------- mma.sync GEMM: tile 128x256, K-stage 32, 3-stage cp.async ----------------
#define RSTR 80
#define A_PL (128 * RSTR)
#define B_PL (256 * RSTR)
#define ST_AH 0
#define ST_AL (A_PL)
#define ST_BH (2 * A_PL)
#define ST_BL (2 * A_PL + B_PL)
#define ST_SZ (2 * A_PL + 2 * B_PL)     // 61440
#define NST 3
#define SMEM_TOT (NST * ST_SZ)          // 184320

template<int KTOT, int NF, bool G1>
__global__ void __launch_bounds__(256, 1)
gemm_mma(const __nv_bfloat16* __restrict__ Ah, const __nv_bfloat16* __restrict__ Al,
         const __nv_bfloat16* __restrict__ Bh, const __nv_bfloat16* __restrict__ Bl,
         const float* __restrict__ bias,
         __nv_bfloat16* __restrict__ Oh, __nv_bfloat16* __restrict__ Ol,
         float* __restrict__ Of, int cap, int tpe) {
    int e = blockIdx.y / tpe, mt = blockIdx.y % tpe;
    if (mt * 128 >= g_cnt[e]) return;
    const int row0 = mt * 128;
    const int n0 = blockIdx.x * 256;
    extern __shared__ char sm[];
    const uint32_t sb = s2u(sm);
    const int tid = threadIdx.x;
    const int wid = tid >> 5, lane = tid & 31;
    const int wm = wid >> 2, wn = wid & 3;

    const size_t arow0 = (size_t)e * cap + row0;
    const __nv_bfloat16* pAh = Ah + arow0 * KTOT;
    const __nv_bfloat16* pAl = Al + arow0 * KTOT;
    const size_t brow0 = (size_t)e * NF + n0;
    const __nv_bfloat16* pBh = Bh + brow0 * KTOT;
    const __nv_bfloat16* pBl = Bl + brow0 * KTOT;

    auto load_stage = [&](int buf, int kbase) {
        uint32_t sbase = sb + buf * ST_SZ;
        #pragma unroll
        for (int j = 0; j < 4; j++) {               // A: 1024 16B-chunks
            int idx = j * 256 + tid;
            int pl = idx >> 9;
            int rem = idx & 511;
            int r = rem >> 2, c = rem & 3;
            const __nv_bfloat16* g = (pl ? pAl : pAh) + (size_t)r * KTOT + kbase + c * 8;
            cp16(sbase + (pl ? ST_AL : ST_AH) + r * RSTR + c * 16, g);
        }
        #pragma unroll
        for (int j = 0; j < 8; j++) {               // B: 2048 16B-chunks
            int idx = j * 256 + tid;
            int pl = idx >> 10;
            int rem = idx & 1023;
            int r = rem >> 2, c = rem & 3;
            const __nv_bfloat16* g = (pl ? pBl : pBh) + (size_t)r * KTOT + kbase + c * 8;
            cp16(sbase + (pl ? ST_BL : ST_BH) + r * RSTR + c * 16, g);
        }
    };

    float acc[4][8][4];
    #pragma unroll
    for (int i = 0; i < 4; i++)
        #pragma unroll
        for (int j = 0; j < 8; j++)
            #pragma unroll
            for (int q = 0; q < 4; q++) acc[i][j][q] = 0.f;

    const uint32_t aAddr = (uint32_t)(wm * 64 + (lane & 15)) * RSTR + (lane >> 4) * 16;
    const uint32_t bAddr = (uint32_t)(wn * 64 + ((lane >> 4) & 1) * 8 + (lane & 7)) * RSTR
                           + ((lane >> 3) & 1) * 16;

    const int NK = KTOT / 32;
    load_stage(0, 0); cp_commit();
    load_stage(1, 32); cp_commit();

    for (int s = 0; s < NK; s++) {
        if (s + 2 < NK) load_stage((s + 2) % NST, (s + 2) * 32);
        cp_commit();
        cp_wait<2>();
        __syncthreads();

        uint32_t sbase = sb + (s % NST) * ST_SZ;
        #pragma unroll
        for (int kk = 0; kk < 2; kk++) {
            uint32_t koff = kk * 32;
            uint32_t ah[4][4], al[4][4];
            #pragma unroll
            for (int mi = 0; mi < 4; mi++) {
                uint32_t base = sbase + aAddr + mi * (16 * RSTR) + koff;
                ldm_x4(ah[mi], base + ST_AH);
                ldm_x4(al[mi], base + ST_AL);
            }
            #pragma unroll
            for (int nq = 0; nq < 4; nq++) {
                uint32_t bb = sbase + bAddr + nq * (16 * RSTR) + koff;
                uint32_t bh[4], bl[4];
                ldm_x4(bh, bb + ST_BH);
                ldm_x4(bl, bb + ST_BL);
                #pragma unroll
                for (int mi = 0; mi < 4; mi++) {
                    mma16816(acc[mi][2 * nq],     ah[mi], bh);
                    mma16816(acc[mi][2 * nq],     ah[mi], bl);
                    mma16816(acc[mi][2 * nq],     al[mi], bh);
                    mma16816(acc[mi][2 * nq + 1], ah[mi], bh + 2);
                    mma16816(acc[mi][2 * nq + 1], ah[mi], bl + 2);
                    mma16816(acc[mi][2 * nq + 1], al[mi], bh + 2);
                }
            }
        }
        __syncthreads();
    }

    // ---------------- epilogue ----------------
    const int colbase = n0 + wn * 64 + (lane & 3) * 2;
    const int rowbase = wm * 64 + (lane >> 2);
    float2 bvv[8];
    #pragma unroll
    for (int ni = 0; ni < 8; ni++)
        bvv[ni] = *(const float2*)(bias + (size_t)e * NF + colbase + ni * 8);
    #pragma unroll
    for (int mi = 0; mi < 4; mi++) {
        #pragma unroll
        for (int half = 0; half < 2; half++) {
            int r = rowbase + mi * 16 + half * 8;
            size_t grow = arow0 + r;
            #pragma unroll
            for (int ni = 0; ni < 8; ni++) {
                int col = colbase + ni * 8;
                float v0 = acc[mi][ni][half * 2 + 0] + bvv[ni].x;
                float v1 = acc[mi][ni][half * 2 + 1] + bvv[ni].y;
                if (G1) {
                    float g0 = gelu_exact(v0), g1 = gelu_exact(v1);
                    *(uint32_t*)(Oh + grow * NF + col) = prmt_hi(g0, g1);
                    *(uint32_t*)(Ol + grow * NF + col) =
                        cvt_bf2(g0 - truncbf(g0), g1 - truncbf(g1));
                } else {
                    *(float2*)(Of + grow * NF + col) = make_float2(v0, v1);
                }
            }
        }
    }
}

// ---------------- combine ----------------
__global__ void combine_kernel(float* __restrict__ out, int N) {
    int gid = blockIdx.x * blockDim.x + threadIdx.x;
    if (gid >= N * (DMODEL / 4)) return;
    int tok = gid >> 7;
    int j = gid & 127;
    int s0 = g_slot[2 * tok], s1 = g_slot[2 * tok + 1];
    float w0 = g_wk[2 * tok], w1 = g_wk[2 * tok + 1];
    float inv = 1.0f / (w0 + w1 + 1e-9f);
    w0 *= inv; w1 *= inv;
    const float4* e0 = (const float4*)(g_EO + (size_t)s0 * DMODEL);
    const float4* e1 = (const float4*)(g_EO + (size_t)s1 * DMODEL);
    float4 a = e0[j], b = e1[j];
    float4 r;
    r.x = w0 * a.x + w1 * b.x;
    r.y = w0 * a.y + w1 * b.y;
    r.z = w0 * a.z + w1 * b.z;
    r.w = w0 * a.w + w1 * b.w;
    ((float4*)out)[gid] = r;
}

// ---------------- launch ----------------
extern "C" void kernel_launch(void* const* d_in, const int* in_sizes, int n_in,
                              void* d_out, int out_size) {
    const float* x  = (const float*)d_in[0];
    const float* Wr = (const float*)d_in[1];
    const float* br = (const float*)d_in[2];
    const float* W1 = (const float*)d_in[3];
    const float* b1 = (const float*)d_in[4];
    const float* W2 = (const float*)d_in[5];
    const float* b2 = (const float*)d_in[6];
    float* out = (float*)d_out;

    int N = in_sizes[0] / DMODEL;
    if (N > NMAX) N = NMAX;
    int cap = (5 * N + 15) / 16;
    if (cap > CAPMAX) cap = CAPMAX;
    int tpe = (cap + 127) / 128;

    void *a1h, *a1l, *hh, *hl, *w1h, *w1l, *w2h, *w2l, *eo;
    cudaGetSymbolAddress(&a1h, g_A1h); cudaGetSymbolAddress(&a1l, g_A1l);
    cudaGetSymbolAddress(&hh,  g_Hh);  cudaGetSymbolAddress(&hl,  g_Hl);
    cudaGetSymbolAddress(&w1h, g_W1h); cudaGetSymbolAddress(&w1l, g_W1l);
    cudaGetSymbolAddress(&w2h, g_W2h); cudaGetSymbolAddress(&w2l, g_W2l);
    cudaGetSymbolAddress(&eo,  g_EO);

    cudaFuncSetAttribute(gemm_mma<DMODEL, DFF, true>,
                         cudaFuncAttributeMaxDynamicSharedMemorySize, SMEM_TOT);
    cudaFuncSetAttribute(gemm_mma<DFF, DMODEL, false>,
                         cudaFuncAttributeMaxDynamicSharedMemorySize, SMEM_TOT);

    router_kernel<<<(N * 32 + 255) / 256, 256>>>(x, Wr, br, N);
    dispatch_kernel<<<1, 1024>>>(N, cap);
    wconvert_kernel<<<dim3(DFF / 32, DMODEL / 32, NEXP), 256>>>(
        W1, (__nv_bfloat16*)w1h, (__nv_bfloat16*)w1l, DMODEL, DFF);
    wconvert_kernel<<<dim3(DMODEL / 32, DFF / 32, NEXP), 256>>>(
        W2, (__nv_bfloat16*)w2h, (__nv_bfloat16*)w2l, DFF, DMODEL);
    gather_kernel<<<(NEXP * cap * 128) / 256, 256>>>(
        x, (__nv_bfloat16*)a1h, (__nv_bfloat16*)a1l);

    dim3 g1(DFF / 256, NEXP * tpe);
    gemm_mma<DMODEL, DFF, true><<<g1, 256, SMEM_TOT>>>(
        (const __nv_bfloat16*)a1h, (const __nv_bfloat16*)a1l,
        (const __nv_bfloat16*)w1h, (const __nv_bfloat16*)w1l,
        b1, (__nv_bfloat16*)hh, (__nv_bfloat16*)hl, nullptr, cap, tpe);

    dim3 g2(DMODEL / 256, NEXP * tpe);
    gemm_mma<DFF, DMODEL, false><<<g2, 256, SMEM_TOT>>>(
        (const __nv_bfloat16*)hh, (const __nv_bfloat16*)hl,
        (const __nv_bfloat16*)w2h, (const __nv_bfloat16*)w2l,
        b2, nullptr, nullptr, (float*)eo, cap, tpe);

    combine_kernel<<<(N * (DMODEL / 4) + 255) / 256, 256>>>(out, N);
}

// round 5
// speedup vs baseline: 4.2973x; 1.2961x over previous
#include <cuda_runtime.h>
#include <cuda_fp16.h>
#include <cstdint>

#define DMODEL 512
#define DFF 2048
#define NEXP 8
#define TOPK 2
#define NMAX 32768
#define CAPMAX 10240
#define EROWS (NEXP * CAPMAX)

typedef unsigned long long ull;

// ---------------- scratch ----------------
__device__ __align__(1024) __half g_A1h[(size_t)EROWS * DMODEL];
__device__ __align__(1024) __half g_A1l[(size_t)EROWS * DMODEL];
__device__ __align__(1024) __half g_Hh [(size_t)EROWS * DFF];
__device__ __align__(1024) __half g_Hl [(size_t)EROWS * DFF];
__device__ __align__(1024) __half g_W1h[(size_t)NEXP * DFF * DMODEL];   // [e][n][k]
__device__ __align__(1024) __half g_W2h[(size_t)NEXP * DMODEL * DFF];   // [e][n][k]
__device__ __align__(1024) float g_EO[(size_t)EROWS * DMODEL];
__device__ int    g_rowidx[EROWS];
__device__ int    g_slot[NMAX * TOPK];
__device__ float  g_wk  [NMAX * TOPK];
__device__ int2   g_ti[NMAX];
__device__ float2 g_tw[NMAX];
__device__ int    g_cnt[NEXP];

// ---------------- helpers ----------------
__device__ __forceinline__ uint32_t s2u(const void* p) {
    uint32_t a;
    asm("{ .reg .u64 t; cvta.to.shared.u64 t, %1; cvt.u32.u64 %0, t; }" : "=r"(a) : "l"(p));
    return a;
}
__device__ __forceinline__ float gelu_exact(float v) {
    return 0.5f * v * (1.0f + erff(v * 0.7071067811865476f));
}
__device__ __forceinline__ uint32_t pack_h2(__half a, __half b) {
    return (uint32_t)__half_as_ushort(a) | ((uint32_t)__half_as_ushort(b) << 16);
}

__device__ __forceinline__ void cp16(uint32_t s, const void* g) {
    asm volatile("cp.async.cg.shared.global [%0], [%1], 16;" :: "r"(s), "l"(g));
}
__device__ __forceinline__ void cp_commit() { asm volatile("cp.async.commit_group;"); }
template<int N> __device__ __forceinline__ void cp_wait() {
    asm volatile("cp.async.wait_group %0;" :: "n"(N));
}
__device__ __forceinline__ void ldm_x4(uint32_t* r, uint32_t a) {
    asm volatile("ldmatrix.sync.aligned.m8n8.x4.shared.b16 {%0,%1,%2,%3}, [%4];"
                 : "=r"(r[0]), "=r"(r[1]), "=r"(r[2]), "=r"(r[3]) : "r"(a));
}
__device__ __forceinline__ void mma16816(float* c, const uint32_t* a, const uint32_t* b) {
    asm volatile(
        "mma.sync.aligned.m16n8k16.row.col.f32.f16.f16.f32 "
        "{%0,%1,%2,%3}, {%4,%5,%6,%7}, {%8,%9}, {%0,%1,%2,%3};"
        : "+f"(c[0]), "+f"(c[1]), "+f"(c[2]), "+f"(c[3])
        : "r"(a[0]), "r"(a[1]), "r"(a[2]), "r"(a[3]), "r"(b[0]), "r"(b[1]));
}

// ---------------- router ----------------
__global__ void router_kernel(const float* __restrict__ x,
                              const float* __restrict__ Wr,
                              const float* __restrict__ br, int N) {
    int warp = (blockIdx.x * blockDim.x + threadIdx.x) >> 5;
    int lane = threadIdx.x & 31;
    if (warp >= N) return;
    const float* xr = x + (size_t)warp * DMODEL;
    float acc[8] = {0, 0, 0, 0, 0, 0, 0, 0};
    for (int d = lane; d < DMODEL; d += 32) {
        float xv = xr[d];
        float4 w0 = *(const float4*)(Wr + (size_t)d * 8);
        float4 w1 = *(const float4*)(Wr + (size_t)d * 8 + 4);
        acc[0] += xv * w0.x; acc[1] += xv * w0.y;
        acc[2] += xv * w0.z; acc[3] += xv * w0.w;
        acc[4] += xv * w1.x; acc[5] += xv * w1.y;
        acc[6] += xv * w1.z; acc[7] += xv * w1.w;
    }
    #pragma unroll
    for (int o = 16; o; o >>= 1)
        #pragma unroll
        for (int e = 0; e < 8; e++)
            acc[e] += __shfl_xor_sync(0xFFFFFFFFu, acc[e], o);
    if (lane == 0) {
        float l[8], p[8];
        float m = -1e30f;
        #pragma unroll
        for (int e = 0; e < 8; e++) { l[e] = acc[e] + br[e]; m = fmaxf(m, l[e]); }
        float s = 0.f;
        #pragma unroll
        for (int e = 0; e < 8; e++) { p[e] = expf(l[e] - m); s += p[e]; }
        float inv = 1.0f / s;
        #pragma unroll
        for (int e = 0; e < 8; e++) p[e] *= inv;
        int i1 = 0; float p1 = p[0];
        #pragma unroll
        for (int e = 1; e < 8; e++) if (p[e] > p1) { p1 = p[e]; i1 = e; }
        int i2 = -1; float p2 = -1.0f;
        #pragma unroll
        for (int e = 0; e < 8; e++) if (e != i1 && p[e] > p2) { p2 = p[e]; i2 = e; }
        float den = p1 + p2 + 1e-9f;
        g_ti[warp] = make_int2(i1, i2);
        g_tw[warp] = make_float2(p1 / den, p2 / den);
    }
}

// ---------------- dispatch ----------------
__global__ void dispatch_kernel(int N, int cap) {
    const int T = 1024;
    int t = threadIdx.x;
    int slots = N * TOPK;
    int C = (slots + T - 1) / T;
    __shared__ int sc[8][1024];
    __shared__ int stot[8];
    int cnt[8] = {0, 0, 0, 0, 0, 0, 0, 0};
    int s0 = t * C, s1 = min(s0 + C, slots);
    for (int s = s0; s < s1; s++) {
        int2 ti = g_ti[s >> 1];
        cnt[(s & 1) ? ti.y : ti.x]++;
    }
    #pragma unroll
    for (int e = 0; e < 8; e++) sc[e][t] = cnt[e];
    __syncthreads();
    if (t < 8) {
        int run = 0;
        for (int i = 0; i < T; i++) { int v = sc[t][i]; sc[t][i] = run; run += v; }
        stot[t] = run;
        g_cnt[t] = min(run, cap);
    }
    __syncthreads();
    int pos[8];
    #pragma unroll
    for (int e = 0; e < 8; e++) pos[e] = sc[e][t];
    for (int s = s0; s < s1; s++) {
        int tok = s >> 1, k = s & 1;
        int2 ti = g_ti[tok];
        float2 tw = g_tw[tok];
        int e = k ? ti.y : ti.x;
        float w = k ? tw.y : tw.x;
        int p = pos[e]++;
        bool keep = p < cap;
        int slot = e * cap + p;
        if (keep) g_rowidx[slot] = tok;
        g_slot[s] = keep ? slot : 0;
        g_wk[s]   = keep ? w : 0.0f;
    }
    for (int e = 0; e < 8; e++) {
        int c = min(stot[e], cap);
        for (int p = c + t; p < cap; p += T) g_rowidx[e * cap + p] = -1;
    }
}

// ---------------- weight convert+transpose: [e][R][C] f32 -> [e][C][R] fp16 (hi only) ----------------
__global__ void wconvert_kernel(const float* __restrict__ src,
                                __half* __restrict__ dh, int R, int C) {
    int e = blockIdx.z;
    int c0 = blockIdx.x * 32, r0 = blockIdx.y * 32;
    __shared__ float t[32][33];
    int tx = threadIdx.x & 31, ty = threadIdx.x >> 5;
    const float* s = src + (size_t)e * R * C;
    #pragma unroll
    for (int i = 0; i < 4; i++)
        t[ty + i * 8][tx] = s[(size_t)(r0 + ty + i * 8) * C + c0 + tx];
    __syncthreads();
    size_t ob = (size_t)e * C * R;
    #pragma unroll
    for (int i = 0; i < 4; i++) {
        int c = c0 + ty + i * 8;
        float v = t[tx][ty + i * 8];
        dh[ob + (size_t)c * R + r0 + tx] = __float2half_rn(v);
    }
}

// ---------------- gather: tokens -> fp16 hi/lo planes ----------------
__global__ void gather_kernel(const float* __restrict__ x,
                              __half* __restrict__ Ah, __half* __restrict__ Al) {
    int gid = blockIdx.x * 256 + threadIdx.x;
    int row = gid >> 7, j = gid & 127;
    int tok = g_rowidx[row];
    float4 v = make_float4(0, 0, 0, 0);
    if (tok >= 0) v = ((const float4*)(x + (size_t)tok * DMODEL))[j];
    __half h0 = __float2half_rn(v.x), h1 = __float2half_rn(v.y);
    __half h2 = __float2half_rn(v.z), h3 = __float2half_rn(v.w);
    __half l0 = __float2half_rn(v.x - __half2float(h0));
    __half l1 = __float2half_rn(v.y - __half2float(h1));
    __half l2 = __float2half_rn(v.z - __half2float(h2));
    __half l3 = __float2half_rn(v.w - __half2float(h3));
    uint2 ph = make_uint2(pack_h2(h0, h1), pack_h2(h2, h3));
    uint2 pl = make_uint2(pack_h2(l0, l1), pack_h2(l2, l3));
    ((uint2*)(Ah + (size_t)row * DMODEL))[j] = ph;
    ((uint2*)(Al + (size_t)row * DMODEL))[j] = pl;
}

// ---------------- mma.sync GEMM: tile 128x256, K-stage 32, 4-stage cp.async ----------------
#define RSTR 80
#define A_PL (128 * RSTR)          // 10240
#define B_PL (256 * RSTR)          // 20480
#define ST_AH 0
#define ST_AL (A_PL)
#define ST_B  (2 * A_PL)
#define ST_SZ (2 * A_PL + B_PL)    // 40960
#define NST 4
#define SMEM_TOT (NST * ST_SZ)     // 163840

template<int KTOT, int NF, bool G1>
__global__ void __launch_bounds__(256, 1)
gemm_mma(const __half* __restrict__ Ah, const __half* __restrict__ Al,
         const __half* __restrict__ Bh,
         const float* __restrict__ bias,
         __half* __restrict__ Oh, __half* __restrict__ Ol,
         float* __restrict__ Of, int cap, int tpe) {
    int e = blockIdx.y / tpe, mt = blockIdx.y % tpe;
    if (mt * 128 >= g_cnt[e]) return;
    const int row0 = mt * 128;
    const int n0 = blockIdx.x * 256;
    extern __shared__ char sm[];
    const uint32_t sb = s2u(sm);
    const int tid = threadIdx.x;
    const int wid = tid >> 5, lane = tid & 31;
    const int wm = wid >> 2, wn = wid & 3;

    const size_t arow0 = (size_t)e * cap + row0;
    const __half* pAh = Ah + arow0 * KTOT;
    const __half* pAl = Al + arow0 * KTOT;
    const __half* pBh = Bh + ((size_t)e * NF + n0) * KTOT;

    auto load_stage = [&](int buf, int kbase) {
        uint32_t sbase = sb + buf * ST_SZ;
        #pragma unroll
        for (int j = 0; j < 4; j++) {               // A: 1024 16B-chunks (2 planes)
            int idx = j * 256 + tid;
            int pl = idx >> 9;
            int rem = idx & 511;
            int r = rem >> 2, c = rem & 3;
            const __half* g = (pl ? pAl : pAh) + (size_t)r * KTOT + kbase + c * 8;
            cp16(sbase + (pl ? ST_AL : ST_AH) + r * RSTR + c * 16, g);
        }
        #pragma unroll
        for (int j = 0; j < 4; j++) {               // B: 1024 16B-chunks (hi plane)
            int idx = j * 256 + tid;
            int r = idx >> 2, c = idx & 3;
            const __half* g = pBh + (size_t)r * KTOT + kbase + c * 8;
            cp16(sbase + ST_B + r * RSTR + c * 16, g);
        }
    };

    float acc[4][8][4];
    #pragma unroll
    for (int i = 0; i < 4; i++)
        #pragma unroll
        for (int j = 0; j < 8; j++)
            #pragma unroll
            for (int q = 0; q < 4; q++) acc[i][j][q] = 0.f;

    const uint32_t aAddr = (uint32_t)(wm * 64 + (lane & 15)) * RSTR + (lane >> 4) * 16;
    const uint32_t bAddr = (uint32_t)(wn * 64 + ((lane >> 4) & 1) * 8 + (lane & 7)) * RSTR
                           + ((lane >> 3) & 1) * 16;

    const int NK = KTOT / 32;
    load_stage(0, 0); cp_commit();
    load_stage(1, 32); cp_commit();
    load_stage(2, 64); cp_commit();

    for (int s = 0; s < NK; s++) {
        if (s + 3 < NK) load_stage((s + 3) % NST, (s + 3) * 32);
        cp_commit();
        cp_wait<3>();
        __syncthreads();

        uint32_t sbase = sb + (s % NST) * ST_SZ;
        #pragma unroll
        for (int kk = 0; kk < 2; kk++) {
            uint32_t koff = kk * 32;
            uint32_t ah[4][4], al[4][4], bh[4][4];
            #pragma unroll
            for (int mi = 0; mi < 4; mi++) {
                uint32_t base = sbase + aAddr + mi * (16 * RSTR) + koff;
                ldm_x4(ah[mi], base + ST_AH);
                ldm_x4(al[mi], base + ST_AL);
            }
            #pragma unroll
            for (int nq = 0; nq < 4; nq++)
                ldm_x4(bh[nq], sbase + ST_B + bAddr + nq * (16 * RSTR) + koff);
            // pass 1: Ah * Bh  (all accs touched once)
            #pragma unroll
            for (int mi = 0; mi < 4; mi++)
                #pragma unroll
                for (int nq = 0; nq < 4; nq++) {
                    mma16816(acc[mi][2 * nq],     ah[mi], bh[nq]);
                    mma16816(acc[mi][2 * nq + 1], ah[mi], bh[nq] + 2);
                }
            // pass 2: Al * Bh
            #pragma unroll
            for (int mi = 0; mi < 4; mi++)
                #pragma unroll
                for (int nq = 0; nq < 4; nq++) {
                    mma16816(acc[mi][2 * nq],     al[mi], bh[nq]);
                    mma16816(acc[mi][2 * nq + 1], al[mi], bh[nq] + 2);
                }
        }
        __syncthreads();
    }

    // ---------------- epilogue ----------------
    const int colbase = n0 + wn * 64 + (lane & 3) * 2;
    const int rowbase = wm * 64 + (lane >> 2);
    float2 bvv[8];
    #pragma unroll
    for (int ni = 0; ni < 8; ni++)
        bvv[ni] = *(const float2*)(bias + (size_t)e * NF + colbase + ni * 8);
    #pragma unroll
    for (int mi = 0; mi < 4; mi++) {
        #pragma unroll
        for (int half = 0; half < 2; half++) {
            int r = rowbase + mi * 16 + half * 8;
            size_t grow = arow0 + r;
            #pragma unroll
            for (int ni = 0; ni < 8; ni++) {
                int col = colbase + ni * 8;
                float v0 = acc[mi][ni][half * 2 + 0] + bvv[ni].x;
                float v1 = acc[mi][ni][half * 2 + 1] + bvv[ni].y;
                if (G1) {
                    float g0 = gelu_exact(v0), g1 = gelu_exact(v1);
                    __half h0 = __float2half_rn(g0), h1 = __float2half_rn(g1);
                    __half l0 = __float2half_rn(g0 - __half2float(h0));
                    __half l1 = __float2half_rn(g1 - __half2float(h1));
                    *(uint32_t*)(Oh + grow * NF + col) = pack_h2(h0, h1);
                    *(uint32_t*)(Ol + grow * NF + col) = pack_h2(l0, l1);
                } else {
                    *(float2*)(Of + grow * NF + col) = make_float2(v0, v1);
                }
            }
        }
    }
}

// ---------------- combine ----------------
__global__ void combine_kernel(float* __restrict__ out, int N) {
    int gid = blockIdx.x * blockDim.x + threadIdx.x;
    if (gid >= N * (DMODEL / 4)) return;
    int tok = gid >> 7;
    int j = gid & 127;
    int s0 = g_slot[2 * tok], s1 = g_slot[2 * tok + 1];
    float w0 = g_wk[2 * tok], w1 = g_wk[2 * tok + 1];
    float inv = 1.0f / (w0 + w1 + 1e-9f);
    w0 *= inv; w1 *= inv;
    const float4* e0 = (const float4*)(g_EO + (size_t)s0 * DMODEL);
    const float4* e1 = (const float4*)(g_EO + (size_t)s1 * DMODEL);
    float4 a = e0[j], b = e1[j];
    float4 r;
    r.x = w0 * a.x + w1 * b.x;
    r.y = w0 * a.y + w1 * b.y;
    r.z = w0 * a.z + w1 * b.z;
    r.w = w0 * a.w + w1 * b.w;
    ((float4*)out)[gid] = r;
}

// ---------------- launch ----------------
extern "C" void kernel_launch(void* const* d_in, const int* in_sizes, int n_in,
                              void* d_out, int out_size) {
    const float* x  = (const float*)d_in[0];
    const float* Wr = (const float*)d_in[1];
    const float* br = (const float*)d_in[2];
    const float* W1 = (const float*)d_in[3];
    const float* b1 = (const float*)d_in[4];
    const float* W2 = (const float*)d_in[5];
    const float* b2 = (const float*)d_in[6];
    float* out = (float*)d_out;

    int N = in_sizes[0] / DMODEL;
    if (N > NMAX) N = NMAX;
    int cap = (5 * N + 15) / 16;
    if (cap > CAPMAX) cap = CAPMAX;
    int tpe = (cap + 127) / 128;

    void *a1h, *a1l, *hh, *hl, *w1h, *w2h, *eo;
    cudaGetSymbolAddress(&a1h, g_A1h); cudaGetSymbolAddress(&a1l, g_A1l);
    cudaGetSymbolAddress(&hh,  g_Hh);  cudaGetSymbolAddress(&hl,  g_Hl);
    cudaGetSymbolAddress(&w1h, g_W1h); cudaGetSymbolAddress(&w2h, g_W2h);
    cudaGetSymbolAddress(&eo,  g_EO);

    cudaFuncSetAttribute(gemm_mma<DMODEL, DFF, true>,
                         cudaFuncAttributeMaxDynamicSharedMemorySize, SMEM_TOT);
    cudaFuncSetAttribute(gemm_mma<DFF, DMODEL, false>,
                         cudaFuncAttributeMaxDynamicSharedMemorySize, SMEM_TOT);

    router_kernel<<<(N * 32 + 255) / 256, 256>>>(x, Wr, br, N);
    dispatch_kernel<<<1, 1024>>>(N, cap);
    wconvert_kernel<<<dim3(DFF / 32, DMODEL / 32, NEXP), 256>>>(
        W1, (__half*)w1h, DMODEL, DFF);
    wconvert_kernel<<<dim3(DMODEL / 32, DFF / 32, NEXP), 256>>>(
        W2, (__half*)w2h, DFF, DMODEL);
    gather_kernel<<<(NEXP * cap * 128) / 256, 256>>>(
        x, (__half*)a1h, (__half*)a1l);

    dim3 g1(DFF / 256, NEXP * tpe);
    gemm_mma<DMODEL, DFF, true><<<g1, 256, SMEM_TOT>>>(
        (const __half*)a1h, (const __half*)a1l, (const __half*)w1h,
        b1, (__half*)hh, (__half*)hl, nullptr, cap, tpe);

    dim3 g2(DMODEL / 256, NEXP * tpe);
    gemm_mma<DFF, DMODEL, false><<<g2, 256, SMEM_TOT>>>(
        (const __half*)hh, (const __half*)hl, (const __half*)w2h,
        b2, nullptr, nullptr, (float*)eo, cap, tpe);

    combine_kernel<<<(N * (DMODEL / 4) + 255) / 256, 256>>>(out, N);
}

// round 6
// speedup vs baseline: 6.7252x; 1.5650x over previous
#include <cuda_runtime.h>
#include <cuda_fp16.h>
#include <cstdint>

#define DMODEL 512
#define DFF 2048
#define NEXP 8
#define TOPK 2
#define NMAX 32768
#define CAPMAX 10240
#define EROWS (NEXP * CAPMAX)

typedef unsigned long long ull;

// ---------------- scratch ----------------
__device__ __align__(1024) __half g_A1h[(size_t)EROWS * DMODEL];
__device__ __align__(1024) __half g_Hh [(size_t)EROWS * DFF];
__device__ __align__(1024) __half g_W1h[(size_t)NEXP * DFF * DMODEL];   // [e][n][k]
__device__ __align__(1024) __half g_W2h[(size_t)NEXP * DMODEL * DFF];   // [e][n][k]
__device__ __align__(1024) float g_EO[(size_t)EROWS * DMODEL];
__device__ int    g_rowidx[EROWS];
__device__ int    g_slot[NMAX * TOPK];
__device__ float  g_wk  [NMAX * TOPK];
__device__ int2   g_ti[NMAX];
__device__ float2 g_tw[NMAX];
__device__ int    g_cnt[NEXP];

// ---------------- helpers ----------------
__device__ __forceinline__ uint32_t s2u(const void* p) {
    uint32_t a;
    asm("{ .reg .u64 t; cvta.to.shared.u64 t, %1; cvt.u32.u64 %0, t; }" : "=r"(a) : "l"(p));
    return a;
}
__device__ __forceinline__ float gelu_exact(float v) {
    return 0.5f * v * (1.0f + erff(v * 0.7071067811865476f));
}
__device__ __forceinline__ uint32_t pack_h2(__half a, __half b) {
    return (uint32_t)__half_as_ushort(a) | ((uint32_t)__half_as_ushort(b) << 16);
}

__device__ __forceinline__ void cp16(uint32_t s, const void* g) {
    asm volatile("cp.async.cg.shared.global [%0], [%1], 16;" :: "r"(s), "l"(g));
}
__device__ __forceinline__ void cp_commit() { asm volatile("cp.async.commit_group;"); }
template<int N> __device__ __forceinline__ void cp_wait() {
    asm volatile("cp.async.wait_group %0;" :: "n"(N));
}
__device__ __forceinline__ void ldm_x4(uint32_t* r, uint32_t a) {
    asm volatile("ldmatrix.sync.aligned.m8n8.x4.shared.b16 {%0,%1,%2,%3}, [%4];"
                 : "=r"(r[0]), "=r"(r[1]), "=r"(r[2]), "=r"(r[3]) : "r"(a));
}
__device__ __forceinline__ void mma16816(float* c, const uint32_t* a, const uint32_t* b) {
    asm volatile(
        "mma.sync.aligned.m16n8k16.row.col.f32.f16.f16.f32 "
        "{%0,%1,%2,%3}, {%4,%5,%6,%7}, {%8,%9}, {%0,%1,%2,%3};"
        : "+f"(c[0]), "+f"(c[1]), "+f"(c[2]), "+f"(c[3])
        : "r"(a[0]), "r"(a[1]), "r"(a[2]), "r"(a[3]), "r"(b[0]), "r"(b[1]));
}

// ---------------- router ----------------
__global__ void router_kernel(const float* __restrict__ x,
                              const float* __restrict__ Wr,
                              const float* __restrict__ br, int N) {
    int warp = (blockIdx.x * blockDim.x + threadIdx.x) >> 5;
    int lane = threadIdx.x & 31;
    if (warp >= N) return;
    const float* xr = x + (size_t)warp * DMODEL;
    float acc[8] = {0, 0, 0, 0, 0, 0, 0, 0};
    for (int d = lane; d < DMODEL; d += 32) {
        float xv = xr[d];
        float4 w0 = *(const float4*)(Wr + (size_t)d * 8);
        float4 w1 = *(const float4*)(Wr + (size_t)d * 8 + 4);
        acc[0] += xv * w0.x; acc[1] += xv * w0.y;
        acc[2] += xv * w0.z; acc[3] += xv * w0.w;
        acc[4] += xv * w1.x; acc[5] += xv * w1.y;
        acc[6] += xv * w1.z; acc[7] += xv * w1.w;
    }
    #pragma unroll
    for (int o = 16; o; o >>= 1)
        #pragma unroll
        for (int e = 0; e < 8; e++)
            acc[e] += __shfl_xor_sync(0xFFFFFFFFu, acc[e], o);
    if (lane == 0) {
        float l[8], p[8];
        float m = -1e30f;
        #pragma unroll
        for (int e = 0; e < 8; e++) { l[e] = acc[e] + br[e]; m = fmaxf(m, l[e]); }
        float s = 0.f;
        #pragma unroll
        for (int e = 0; e < 8; e++) { p[e] = expf(l[e] - m); s += p[e]; }
        float inv = 1.0f / s;
        #pragma unroll
        for (int e = 0; e < 8; e++) p[e] *= inv;
        int i1 = 0; float p1 = p[0];
        #pragma unroll
        for (int e = 1; e < 8; e++) if (p[e] > p1) { p1 = p[e]; i1 = e; }
        int i2 = -1; float p2 = -1.0f;
        #pragma unroll
        for (int e = 0; e < 8; e++) if (e != i1 && p[e] > p2) { p2 = p[e]; i2 = e; }
        float den = p1 + p2 + 1e-9f;
        g_ti[warp] = make_int2(i1, i2);
        g_tw[warp] = make_float2(p1 / den, p2 / den);
    }
}

// ---------------- dispatch ----------------
__global__ void dispatch_kernel(int N, int cap) {
    const int T = 1024;
    int t = threadIdx.x;
    int slots = N * TOPK;
    int C = (slots + T - 1) / T;
    __shared__ int sc[8][1024];
    __shared__ int stot[8];
    int cnt[8] = {0, 0, 0, 0, 0, 0, 0, 0};
    int s0 = t * C, s1 = min(s0 + C, slots);
    for (int s = s0; s < s1; s++) {
        int2 ti = g_ti[s >> 1];
        cnt[(s & 1) ? ti.y : ti.x]++;
    }
    #pragma unroll
    for (int e = 0; e < 8; e++) sc[e][t] = cnt[e];
    __syncthreads();
    if (t < 8) {
        int run = 0;
        for (int i = 0; i < T; i++) { int v = sc[t][i]; sc[t][i] = run; run += v; }
        stot[t] = run;
        g_cnt[t] = min(run, cap);
    }
    __syncthreads();
    int pos[8];
    #pragma unroll
    for (int e = 0; e < 8; e++) pos[e] = sc[e][t];
    for (int s = s0; s < s1; s++) {
        int tok = s >> 1, k = s & 1;
        int2 ti = g_ti[tok];
        float2 tw = g_tw[tok];
        int e = k ? ti.y : ti.x;
        float w = k ? tw.y : tw.x;
        int p = pos[e]++;
        bool keep = p < cap;
        int slot = e * cap + p;
        if (keep) g_rowidx[slot] = tok;
        g_slot[s] = keep ? slot : 0;
        g_wk[s]   = keep ? w : 0.0f;
    }
    for (int e = 0; e < 8; e++) {
        int c = min(stot[e], cap);
        for (int p = c + t; p < cap; p += T) g_rowidx[e * cap + p] = -1;
    }
}

// ---------------- weight convert+transpose: [e][R][C] f32 -> [e][C][R] fp16 ----------------
__global__ void wconvert_kernel(const float* __restrict__ src,
                                __half* __restrict__ dh, int R, int C) {
    int e = blockIdx.z;
    int c0 = blockIdx.x * 32, r0 = blockIdx.y * 32;
    __shared__ float t[32][33];
    int tx = threadIdx.x & 31, ty = threadIdx.x >> 5;
    const float* s = src + (size_t)e * R * C;
    #pragma unroll
    for (int i = 0; i < 4; i++)
        t[ty + i * 8][tx] = s[(size_t)(r0 + ty + i * 8) * C + c0 + tx];
    __syncthreads();
    size_t ob = (size_t)e * C * R;
    #pragma unroll
    for (int i = 0; i < 4; i++) {
        int c = c0 + ty + i * 8;
        float v = t[tx][ty + i * 8];
        dh[ob + (size_t)c * R + r0 + tx] = __float2half_rn(v);
    }
}

// ---------------- gather: tokens -> fp16 plane ----------------
__global__ void gather_kernel(const float* __restrict__ x, __half* __restrict__ Ah) {
    int gid = blockIdx.x * 256 + threadIdx.x;
    int row = gid >> 7, j = gid & 127;
    int tok = g_rowidx[row];
    float4 v = make_float4(0, 0, 0, 0);
    if (tok >= 0) v = ((const float4*)(x + (size_t)tok * DMODEL))[j];
    uint2 ph = make_uint2(pack_h2(__float2half_rn(v.x), __float2half_rn(v.y)),
                          pack_h2(__float2half_rn(v.z), __float2half_rn(v.w)));
    ((uint2*)(Ah + (size_t)row * DMODEL))[j] = ph;
}

// ---------------- fp16 mma.sync GEMM: tile 128x256, K-stage 32, 5-stage cp.async ----------------
#define RSTR 80
#define A_PL (128 * RSTR)          // 10240
#define B_PL (256 * RSTR)          // 20480
#define ST_A  0
#define ST_B  (A_PL)
#define ST_SZ (A_PL + B_PL)        // 30720
#define NST 5
#define SMEM_TOT (NST * ST_SZ)     // 153600

template<int KTOT, int NF, bool G1>
__global__ void __launch_bounds__(256, 1)
gemm_mma(const __half* __restrict__ Ah, const __half* __restrict__ Bh,
         const float* __restrict__ bias,
         __half* __restrict__ Oh, float* __restrict__ Of, int cap, int tpe) {
    int e = blockIdx.y / tpe, mt = blockIdx.y % tpe;
    if (mt * 128 >= g_cnt[e]) return;
    const int row0 = mt * 128;
    const int n0 = blockIdx.x * 256;
    extern __shared__ char sm[];
    const uint32_t sb = s2u(sm);
    const int tid = threadIdx.x;
    const int wid = tid >> 5, lane = tid & 31;
    const int wm = wid >> 2, wn = wid & 3;

    const size_t arow0 = (size_t)e * cap + row0;
    const __half* pA = Ah + arow0 * KTOT;
    const __half* pB = Bh + ((size_t)e * NF + n0) * KTOT;

    auto load_stage = [&](int buf, int kbase) {
        uint32_t sbase = sb + buf * ST_SZ;
        #pragma unroll
        for (int j = 0; j < 2; j++) {               // A: 512 16B-chunks
            int idx = j * 256 + tid;
            int r = idx >> 2, c = idx & 3;
            cp16(sbase + ST_A + r * RSTR + c * 16, pA + (size_t)r * KTOT + kbase + c * 8);
        }
        #pragma unroll
        for (int j = 0; j < 4; j++) {               // B: 1024 16B-chunks
            int idx = j * 256 + tid;
            int r = idx >> 2, c = idx & 3;
            cp16(sbase + ST_B + r * RSTR + c * 16, pB + (size_t)r * KTOT + kbase + c * 8);
        }
    };

    float acc[4][8][4];
    #pragma unroll
    for (int i = 0; i < 4; i++)
        #pragma unroll
        for (int j = 0; j < 8; j++)
            #pragma unroll
            for (int q = 0; q < 4; q++) acc[i][j][q] = 0.f;

    const uint32_t aAddr = (uint32_t)(wm * 64 + (lane & 15)) * RSTR + (lane >> 4) * 16;
    const uint32_t bAddr = (uint32_t)(wn * 64 + ((lane >> 4) & 1) * 8 + (lane & 7)) * RSTR
                           + ((lane >> 3) & 1) * 16;

    const int NK = KTOT / 32;
    load_stage(0, 0);  cp_commit();
    load_stage(1, 32); cp_commit();
    load_stage(2, 64); cp_commit();
    load_stage(3, 96); cp_commit();

    for (int s = 0; s < NK; s++) {
        cp_wait<3>();
        __syncthreads();

        uint32_t sbase = sb + (s % NST) * ST_SZ;
        #pragma unroll
        for (int kk = 0; kk < 2; kk++) {
            uint32_t koff = kk * 32;
            uint32_t ah[4][4], bh[4][4];
            #pragma unroll
            for (int mi = 0; mi < 4; mi++)
                ldm_x4(ah[mi], sbase + ST_A + aAddr + mi * (16 * RSTR) + koff);
            #pragma unroll
            for (int nq = 0; nq < 4; nq++)
                ldm_x4(bh[nq], sbase + ST_B + bAddr + nq * (16 * RSTR) + koff);
            #pragma unroll
            for (int mi = 0; mi < 4; mi++)
                #pragma unroll
                for (int nq = 0; nq < 4; nq++) {
                    mma16816(acc[mi][2 * nq],     ah[mi], bh[nq]);
                    mma16816(acc[mi][2 * nq + 1], ah[mi], bh[nq] + 2);
                }
        }

        if (s + 4 < NK) load_stage((s + 4) % NST, (s + 4) * 32);
        cp_commit();
    }

    // ---------------- epilogue ----------------
    const int colbase = n0 + wn * 64 + (lane & 3) * 2;
    const int rowbase = wm * 64 + (lane >> 2);
    float2 bvv[8];
    #pragma unroll
    for (int ni = 0; ni < 8; ni++)
        bvv[ni] = *(const float2*)(bias + (size_t)e * NF + colbase + ni * 8);
    #pragma unroll
    for (int mi = 0; mi < 4; mi++) {
        #pragma unroll
        for (int half = 0; half < 2; half++) {
            int r = rowbase + mi * 16 + half * 8;
            size_t grow = arow0 + r;
            #pragma unroll
            for (int ni = 0; ni < 8; ni++) {
                int col = colbase + ni * 8;
                float v0 = acc[mi][ni][half * 2 + 0] + bvv[ni].x;
                float v1 = acc[mi][ni][half * 2 + 1] + bvv[ni].y;
                if (G1) {
                    float g0 = gelu_exact(v0), g1 = gelu_exact(v1);
                    *(uint32_t*)(Oh + grow * NF + col) =
                        pack_h2(__float2half_rn(g0), __float2half_rn(g1));
                } else {
                    *(float2*)(Of + grow * NF + col) = make_float2(v0, v1);
                }
            }
        }
    }
}

// ---------------- combine ----------------
__global__ void combine_kernel(float* __restrict__ out, int N) {
    int gid = blockIdx.x * blockDim.x + threadIdx.x;
    if (gid >= N * (DMODEL / 4)) return;
    int tok = gid >> 7;
    int j = gid & 127;
    int s0 = g_slot[2 * tok], s1 = g_slot[2 * tok + 1];
    float w0 = g_wk[2 * tok], w1 = g_wk[2 * tok + 1];
    float inv = 1.0f / (w0 + w1 + 1e-9f);
    w0 *= inv; w1 *= inv;
    const float4* e0 = (const float4*)(g_EO + (size_t)s0 * DMODEL);
    const float4* e1 = (const float4*)(g_EO + (size_t)s1 * DMODEL);
    float4 a = e0[j], b = e1[j];
    float4 r;
    r.x = w0 * a.x + w1 * b.x;
    r.y = w0 * a.y + w1 * b.y;
    r.z = w0 * a.z + w1 * b.z;
    r.w = w0 * a.w + w1 * b.w;
    ((float4*)out)[gid] = r;
}

// ---------------- launch ----------------
extern "C" void kernel_launch(void* const* d_in, const int* in_sizes, int n_in,
                              void* d_out, int out_size) {
    const float* x  = (const float*)d_in[0];
    const float* Wr = (const float*)d_in[1];
    const float* br = (const float*)d_in[2];
    const float* W1 = (const float*)d_in[3];
    const float* b1 = (const float*)d_in[4];
    const float* W2 = (const float*)d_in[5];
    const float* b2 = (const float*)d_in[6];
    float* out = (float*)d_out;

    int N = in_sizes[0] / DMODEL;
    if (N > NMAX) N = NMAX;
    int cap = (5 * N + 15) / 16;
    if (cap > CAPMAX) cap = CAPMAX;
    int tpe = (cap + 127) / 128;

    void *a1h, *hh, *w1h, *w2h, *eo;
    cudaGetSymbolAddress(&a1h, g_A1h);
    cudaGetSymbolAddress(&hh,  g_Hh);
    cudaGetSymbolAddress(&w1h, g_W1h); cudaGetSymbolAddress(&w2h, g_W2h);
    cudaGetSymbolAddress(&eo,  g_EO);

    cudaFuncSetAttribute(gemm_mma<DMODEL, DFF, true>,
                         cudaFuncAttributeMaxDynamicSharedMemorySize, SMEM_TOT);
    cudaFuncSetAttribute(gemm_mma<DFF, DMODEL, false>,
                         cudaFuncAttributeMaxDynamicSharedMemorySize, SMEM_TOT);

    router_kernel<<<(N * 32 + 255) / 256, 256>>>(x, Wr, br, N);
    dispatch_kernel<<<1, 1024>>>(N, cap);
    wconvert_kernel<<<dim3(DFF / 32, DMODEL / 32, NEXP), 256>>>(
        W1, (__half*)w1h, DMODEL, DFF);
    wconvert_kernel<<<dim3(DMODEL / 32, DFF / 32, NEXP), 256>>>(
        W2, (__half*)w2h, DFF, DMODEL);
    gather_kernel<<<(NEXP * cap * 128) / 256, 256>>>(x, (__half*)a1h);

    dim3 g1(DFF / 256, NEXP * tpe);
    gemm_mma<DMODEL, DFF, true><<<g1, 256, SMEM_TOT>>>(
        (const __half*)a1h, (const __half*)w1h, b1,
        (__half*)hh, nullptr, cap, tpe);

    dim3 g2(DMODEL / 256, NEXP * tpe);
    gemm_mma<DFF, DMODEL, false><<<g2, 256, SMEM_TOT>>>(
        (const __half*)hh, (const __half*)w2h, b2,
        nullptr, (float*)eo, cap, tpe);

    combine_kernel<<<(N * (DMODEL / 4) + 255) / 256, 256>>>(out, N);
}